// round 7
// baseline (speedup 1.0000x reference)
#include <cuda_runtime.h>
#include <cuda_bf16.h>
#include <cuda_fp16.h>
#include <stdint.h>

#define NP     4096
#define DF     256
#define TOPK   100
#define NBINS  2048      // fp16 bits >> 4  (max 0x7FFF>>4 = 2047)
#define CAP    65536

// ---- scratch (static device globals; no allocation in kernel_launch) ----
__device__ __nv_bfloat16 g_c1b[NP * DF];
__device__ __nv_bfloat16 g_c2b[NP * DF];
__device__ float         g_sq1[NP];
__device__ float         g_sq2[NP];
__device__ __half        g_d2h[(size_t)NP * NP];   // 32 MB fp16 squared distances
__device__ unsigned int  g_hist[NBINS];
__device__ int           g_threshBin;
__device__ int           g_candCount;
__device__ float         g_cand[CAP];

__device__ __forceinline__ uint32_t smem_u32(const void* p) {
    uint32_t a;
    asm("{ .reg .u64 t; cvta.to.shared.u64 t, %1; cvt.u32.u64 %0, t; }" : "=r"(a) : "l"(p));
    return a;
}

#define LDSM_X4(r0, r1, r2, r3, addr)                                          \
    asm volatile("ldmatrix.sync.aligned.m8n8.x4.shared.b16 {%0,%1,%2,%3}, [%4];" \
        : "=r"(r0), "=r"(r1), "=r"(r2), "=r"(r3) : "r"(addr))

#define MMA16816(c, a0, a1, a2, a3, b0, b1)                                    \
    asm volatile("mma.sync.aligned.m16n8k16.row.col.f32.bf16.bf16.f32 "        \
        "{%0,%1,%2,%3}, {%4,%5,%6,%7}, {%8,%9}, {%0,%1,%2,%3};"                \
        : "+f"((c)[0]), "+f"((c)[1]), "+f"((c)[2]), "+f"((c)[3])               \
        : "r"(a0), "r"(a1), "r"(a2), "r"(a3), "r"(b0), "r"(b1))

// ---- dynamic SMEM layout for k_dist (bytes) ----
// padded bf16 tiles: 128 rows x 264 elems (528 B row) -> conflict-free ldmatrix
#define PADROW  264
#define SM_HIST 0                          // 2048 x u32 = 8192
#define SM_SP   8192                       // 128 f32
#define SM_SQ   8704                       // 128 f32
#define SM_A    9216                       // 128*528 = 67584
#define SM_B    (SM_A + 128 * PADROW * 2)
#define SM_TOT  (SM_B + 128 * PADROW * 2)  // 144384

// ================= kernels =================

__global__ void k_init() {
    int i = blockIdx.x * blockDim.x + threadIdx.x;
    if (i < NBINS) g_hist[i] = 0u;
    if (i == 0) g_candCount = 0;
}

// gather picked rows (-> bf16 copies) + exact fp32 squared norms
__global__ void k_gather(const float* __restrict__ fm,
                         const int* __restrict__ ids1,
                         const int* __restrict__ ids2) {
    int row = blockIdx.x;
    const int* ids = blockIdx.y ? ids2 : ids1;
    __nv_bfloat16* C = blockIdx.y ? g_c2b : g_c1b;
    float*        SQ = blockIdx.y ? g_sq2 : g_sq1;

    int id = ids[row];
    float4 v = ((const float4*)(fm + (size_t)id * DF))[threadIdx.x];  // 64 thr * 4

    unsigned lo = ((unsigned)__bfloat16_as_ushort(__float2bfloat16(v.y)) << 16) |
                   (unsigned)__bfloat16_as_ushort(__float2bfloat16(v.x));
    unsigned hi = ((unsigned)__bfloat16_as_ushort(__float2bfloat16(v.w)) << 16) |
                   (unsigned)__bfloat16_as_ushort(__float2bfloat16(v.z));
    *(uint2*)&C[(size_t)row * DF + threadIdx.x * 4] = make_uint2(lo, hi);

    float s = v.x * v.x + v.y * v.y + v.z * v.z + v.w * v.w;
    #pragma unroll
    for (int o = 16; o; o >>= 1) s += __shfl_down_sync(0xffffffffu, s, o);
    __shared__ float ws[2];
    if ((threadIdx.x & 31) == 0) ws[threadIdx.x >> 5] = s;
    __syncthreads();
    if (threadIdx.x == 0) SQ[row] = ws[0] + ws[1];
}

// 128x128 tile of squared distances via bf16 mma.sync + fine-binned histogram
__global__ __launch_bounds__(256, 1) void k_dist() {
    extern __shared__ char sm[];
    const uint32_t sb = smem_u32(sm);
    const int t = threadIdx.x, lane = t & 31, w = t >> 5;
    const int p0 = blockIdx.y * 128, q0 = blockIdx.x * 128;

    unsigned* hist = (unsigned*)(sm + SM_HIST);
    for (int i = t; i < NBINS; i += 256) hist[i] = 0u;
    if (t < 128)       ((float*)(sm + SM_SP))[t]       = g_sq1[p0 + t];
    else               ((float*)(sm + SM_SQ))[t - 128] = g_sq2[q0 + t - 128];

    // stage both 128x256 bf16 tiles (padded rows of 264)
    #pragma unroll
    for (int i = 0; i < 16; i++) {
        int idx = i * 256 + t;
        int r = idx >> 5, c = idx & 31;                     // c: 16B chunk
        uint4 va = *(const uint4*)&g_c1b[(size_t)(p0 + r) * DF + c * 8];
        uint4 vb = *(const uint4*)&g_c2b[(size_t)(q0 + r) * DF + c * 8];
        *(uint4*)(sm + SM_A + r * (PADROW * 2) + c * 16) = va;
        *(uint4*)(sm + SM_B + r * (PADROW * 2) + c * 16) = vb;
    }
    __syncthreads();

    // warp layout: 4 warps along M (32 rows each), 2 along N (64 cols each)
    const int mbase = (w & 3) * 32;
    const int nbase = (w >> 2) * 64;

    uint32_t aAddr[2], bAddr[4];
    #pragma unroll
    for (int i = 0; i < 2; i++) {
        int row = mbase + i * 16 + (lane & 15);
        aAddr[i] = sb + SM_A + row * (PADROW * 2) + (lane >> 4) * 16;
    }
    #pragma unroll
    for (int jp = 0; jp < 4; jp++) {
        int row = nbase + jp * 16 + (lane & 7) + ((lane >> 4) & 1) * 8;
        bAddr[jp] = sb + SM_B + row * (PADROW * 2) + ((lane >> 3) & 1) * 16;
    }

    float c[2][8][4];
    #pragma unroll
    for (int i = 0; i < 2; i++)
        #pragma unroll
        for (int j = 0; j < 8; j++)
            #pragma unroll
            for (int r = 0; r < 4; r++) c[i][j][r] = 0.f;

    #pragma unroll
    for (int ks = 0; ks < 16; ks++) {           // K = 16 steps of 16
        const uint32_t ko = ks * 32;
        uint32_t a[2][4], b[8][2];
        #pragma unroll
        for (int i = 0; i < 2; i++)
            LDSM_X4(a[i][0], a[i][1], a[i][2], a[i][3], aAddr[i] + ko);
        #pragma unroll
        for (int jp = 0; jp < 4; jp++)
            LDSM_X4(b[2 * jp][0], b[2 * jp][1], b[2 * jp + 1][0], b[2 * jp + 1][1],
                    bAddr[jp] + ko);
        #pragma unroll
        for (int i = 0; i < 2; i++)
            #pragma unroll
            for (int j = 0; j < 8; j++)
                MMA16816(c[i][j], a[i][0], a[i][1], a[i][2], a[i][3], b[j][0], b[j][1]);
    }

    // epilogue: d2 = sp + sq - 2*dot (fp16), warp-aggregated histogram, store
    const float* sps = (const float*)(sm + SM_SP);
    const float* sqs = (const float*)(sm + SM_SQ);

    #pragma unroll
    for (int i = 0; i < 2; i++) {
        const int r0 = mbase + i * 16 + (lane >> 2);
        const float sp0 = sps[r0], sp1 = sps[r0 + 8];
        #pragma unroll
        for (int j = 0; j < 8; j++) {
            const int cl = nbase + j * 8 + (lane & 3) * 2;
            const float sq0 = sqs[cl], sq1 = sqs[cl + 1];
            float d0 = fmaxf(sp0 + sq0 - 2.f * c[i][j][0], 0.f);
            float d1 = fmaxf(sp0 + sq1 - 2.f * c[i][j][1], 0.f);
            float d2v = fmaxf(sp1 + sq0 - 2.f * c[i][j][2], 0.f);
            float d3 = fmaxf(sp1 + sq1 - 2.f * c[i][j][3], 0.f);
            __half2 h01 = __floats2half2_rn(d0, d1);
            __half2 h23 = __floats2half2_rn(d2v, d3);

            unsigned u01 = *(unsigned*)&h01, u23 = *(unsigned*)&h23;
            unsigned bins[4] = { (u01 & 0xFFFFu) >> 4, u01 >> 20,
                                 (u23 & 0xFFFFu) >> 4, u23 >> 20 };
            #pragma unroll
            for (int v = 0; v < 4; v++) {
                unsigned bin = bins[v];
                unsigned m = __match_any_sync(0xffffffffu, bin);
                if (lane == (__ffs(m) - 1))
                    atomicAdd(&hist[bin], (unsigned)__popc(m));
            }

            *(__half2*)&g_d2h[(size_t)(p0 + r0)     * NP + q0 + cl] = h01;
            *(__half2*)&g_d2h[(size_t)(p0 + r0 + 8) * NP + q0 + cl] = h23;
        }
    }
    __syncthreads();
    for (int i = t; i < NBINS; i += 256) {
        unsigned h = hist[i];
        if (h) atomicAdd(&g_hist[i], h);
    }
}

// parallel suffix-scan threshold: bin containing the rank-TOPK value
__global__ __launch_bounds__(1024) void k_thresh() {
    __shared__ unsigned scan[1024];
    const int t = threadIdx.x;
    const int btop = NBINS - 1 - 2 * t;          // group t: 2 bins descending
    unsigned h0 = g_hist[btop], h1 = g_hist[btop - 1];
    unsigned p = h0 + h1;
    scan[t] = p;
    __syncthreads();
    #pragma unroll
    for (int o = 1; o < 1024; o <<= 1) {
        unsigned v = (t >= o) ? scan[t - o] : 0u;
        __syncthreads();
        if (t >= o) scan[t] += v;
        __syncthreads();
    }
    unsigned excl = scan[t] - p;
    if (excl < TOPK && excl + p >= TOPK) {       // exactly one thread crosses
        unsigned cum = excl + h0;
        g_threshBin = (cum >= TOPK) ? btop : btop - 1;
    }
}

// compact all fp16 values whose bin >= threshold
__global__ void k_compact() {
    size_t i = (size_t)blockIdx.x * blockDim.x + threadIdx.x;
    const uint4 v = ((const uint4*)g_d2h)[i];      // 8 halves
    const unsigned tb = (unsigned)g_threshBin;
    unsigned words[4] = {v.x, v.y, v.z, v.w};
    #pragma unroll
    for (int wI = 0; wI < 4; wI++) {
        unsigned lo = words[wI] & 0xFFFFu, hi = words[wI] >> 16;
        if ((lo >> 4) >= tb) {
            int p = atomicAdd(&g_candCount, 1);
            if (p < CAP) g_cand[p] = __half2float(__ushort_as_half((unsigned short)lo));
        }
        if ((hi >> 4) >= tb) {
            int p = atomicAdd(&g_candCount, 1);
            if (p < CAP) g_cand[p] = __half2float(__ushort_as_half((unsigned short)hi));
        }
    }
}

// exact top-100 over candidates, mean of sqrt (descending -> deterministic)
__global__ __launch_bounds__(1024) void k_select(float* __restrict__ out) {
    __shared__ float red[1024];
    __shared__ int   redi[1024];
    __shared__ float s_sum;
    const int t = threadIdx.x;
    int n = g_candCount;
    if (n > CAP) n = CAP;
    if (t == 0) s_sum = 0.f;
    __syncthreads();

    for (int it = 0; it < TOPK; it++) {
        float m = -1.f; int mi = -1;
        for (int i = t; i < n; i += 1024) {
            float v = g_cand[i];
            if (v > m) { m = v; mi = i; }
        }
        red[t] = m; redi[t] = mi;
        __syncthreads();
        #pragma unroll
        for (int s = 512; s > 0; s >>= 1) {
            if (t < s && red[t + s] > red[t]) { red[t] = red[t + s]; redi[t] = redi[t + s]; }
            __syncthreads();
        }
        if (t == 0 && redi[0] >= 0) {
            s_sum += sqrtf(red[0]);
            g_cand[redi[0]] = -1.f;
        }
        __syncthreads();
    }
    if (t == 0) *out = s_sum / (float)TOPK;
}

extern "C" void kernel_launch(void* const* d_in, const int* in_sizes, int n_in,
                              void* d_out, int out_size) {
    const float* fm   = (const float*)d_in[0];
    const int*   ids1 = (const int*)d_in[1];
    const int*   ids2 = (const int*)d_in[2];
    float* out = (float*)d_out;

    static int smem_set = 0;
    if (!smem_set) {
        cudaFuncSetAttribute(k_dist, cudaFuncAttributeMaxDynamicSharedMemorySize, SM_TOT);
        smem_set = 1;
    }

    k_init<<<(NBINS + 255) / 256, 256>>>();
    k_gather<<<dim3(NP, 2), 64>>>(fm, ids1, ids2);
    k_dist<<<dim3(NP / 128, NP / 128), 256, SM_TOT>>>();
    k_thresh<<<1, 1024>>>();
    k_compact<<<(NP * NP / 8) / 256, 256>>>();   // uint4 = 8 halves per thread
    k_select<<<1, 1024>>>(out);
}

// round 8
// speedup vs baseline: 1.4319x; 1.4319x over previous
#include <cuda_runtime.h>
#include <cuda_bf16.h>
#include <cuda_fp16.h>
#include <stdint.h>

#define NP     4096
#define DF     256
#define TOPK   100
#define NBINS  2048      // fp16 bits >> 4
#define CAP    65536

// ---- scratch (static device globals; no allocation in kernel_launch) ----
__device__ __nv_bfloat16 g_c1b[NP * DF];
__device__ __nv_bfloat16 g_c2b[NP * DF];
__device__ float         g_sq1[NP];
__device__ float         g_sq2[NP];
__device__ __half        g_d2h[(size_t)NP * NP];   // 32 MB fp16 squared distances
__device__ unsigned int  g_hist[NBINS];
__device__ int           g_threshBin;
__device__ int           g_candCount;
__device__ float         g_cand[CAP];

__device__ __forceinline__ uint32_t smem_u32(const void* p) {
    uint32_t a;
    asm("{ .reg .u64 t; cvta.to.shared.u64 t, %1; cvt.u32.u64 %0, t; }" : "=r"(a) : "l"(p));
    return a;
}

#define LDSM_X4(r0, r1, r2, r3, addr)                                          \
    asm volatile("ldmatrix.sync.aligned.m8n8.x4.shared.b16 {%0,%1,%2,%3}, [%4];" \
        : "=r"(r0), "=r"(r1), "=r"(r2), "=r"(r3) : "r"(addr))

#define MMA16816(c, a0, a1, a2, a3, b0, b1)                                    \
    asm volatile("mma.sync.aligned.m16n8k16.row.col.f32.bf16.bf16.f32 "        \
        "{%0,%1,%2,%3}, {%4,%5,%6,%7}, {%8,%9}, {%0,%1,%2,%3};"                \
        : "+f"((c)[0]), "+f"((c)[1]), "+f"((c)[2]), "+f"((c)[3])               \
        : "r"(a0), "r"(a1), "r"(a2), "r"(a3), "r"(b0), "r"(b1))

// ---- dynamic SMEM layout for k_dist (bytes) ----
// K processed in 2 chunks of 128: tiles 128 rows x 136 bf16 (272 B rows,
// conflict-free ldmatrix: 272/4 mod 32 = 4 -> 8-row groups span all banks)
#define PADROW  136
#define SM_HIST 0                          // 2048 x u32 = 8192
#define SM_SP   8192                       // 128 f32
#define SM_SQ   8704                       // 128 f32
#define SM_A    9216                       // 128*272 = 34816
#define SM_B    (SM_A + 128 * PADROW * 2)
#define SM_TOT  (SM_B + 128 * PADROW * 2)  // 78848 -> 2 CTAs/SM

// ================= kernels =================

__global__ void k_init() {
    int i = blockIdx.x * blockDim.x + threadIdx.x;
    if (i < NBINS) g_hist[i] = 0u;
    if (i == 0) g_candCount = 0;
}

// gather picked rows (-> bf16 copies) + exact fp32 squared norms
__global__ void k_gather(const float* __restrict__ fm,
                         const int* __restrict__ ids1,
                         const int* __restrict__ ids2) {
    int row = blockIdx.x;
    const int* ids = blockIdx.y ? ids2 : ids1;
    __nv_bfloat16* C = blockIdx.y ? g_c2b : g_c1b;
    float*        SQ = blockIdx.y ? g_sq2 : g_sq1;

    int id = ids[row];
    float4 v = ((const float4*)(fm + (size_t)id * DF))[threadIdx.x];  // 64 thr * 4

    unsigned lo = ((unsigned)__bfloat16_as_ushort(__float2bfloat16(v.y)) << 16) |
                   (unsigned)__bfloat16_as_ushort(__float2bfloat16(v.x));
    unsigned hi = ((unsigned)__bfloat16_as_ushort(__float2bfloat16(v.w)) << 16) |
                   (unsigned)__bfloat16_as_ushort(__float2bfloat16(v.z));
    *(uint2*)&C[(size_t)row * DF + threadIdx.x * 4] = make_uint2(lo, hi);

    float s = v.x * v.x + v.y * v.y + v.z * v.z + v.w * v.w;
    #pragma unroll
    for (int o = 16; o; o >>= 1) s += __shfl_down_sync(0xffffffffu, s, o);
    __shared__ float ws[2];
    if ((threadIdx.x & 31) == 0) ws[threadIdx.x >> 5] = s;
    __syncthreads();
    if (threadIdx.x == 0) SQ[row] = ws[0] + ws[1];
}

// 128x128 tile of squared distances via bf16 mma.sync (2 CTAs/SM) + histogram
__global__ __launch_bounds__(256, 2) void k_dist() {
    extern __shared__ char sm[];
    const uint32_t sb = smem_u32(sm);
    const int t = threadIdx.x, lane = t & 31, w = t >> 5;
    const int p0 = blockIdx.y * 128, q0 = blockIdx.x * 128;

    unsigned* hist = (unsigned*)(sm + SM_HIST);
    for (int i = t; i < NBINS; i += 256) hist[i] = 0u;
    if (t < 128)       ((float*)(sm + SM_SP))[t]       = g_sq1[p0 + t];
    else               ((float*)(sm + SM_SQ))[t - 128] = g_sq2[q0 + t - 128];

    // warp layout: 4 warps along M (32 rows each), 2 along N (64 cols each)
    const int mbase = (w & 3) * 32;
    const int nbase = (w >> 2) * 64;

    uint32_t aAddr[2], bAddr[4];
    #pragma unroll
    for (int i = 0; i < 2; i++) {
        int row = mbase + i * 16 + (lane & 15);
        aAddr[i] = sb + SM_A + row * (PADROW * 2) + (lane >> 4) * 16;
    }
    #pragma unroll
    for (int jp = 0; jp < 4; jp++) {
        int row = nbase + jp * 16 + (lane & 7) + ((lane >> 4) & 1) * 8;
        bAddr[jp] = sb + SM_B + row * (PADROW * 2) + ((lane >> 3) & 1) * 16;
    }

    float c[2][8][4];
    #pragma unroll
    for (int i = 0; i < 2; i++)
        #pragma unroll
        for (int j = 0; j < 8; j++)
            #pragma unroll
            for (int r = 0; r < 4; r++) c[i][j][r] = 0.f;

    for (int kc = 0; kc < 2; kc++) {
        // stage 128x128 bf16 K-chunk of both tiles (8 x 16B per tile per thread)
        #pragma unroll
        for (int i = 0; i < 8; i++) {
            int idx = i * 256 + t;
            int r = idx >> 4, cc = idx & 15;                // cc: 16B chunk
            uint4 va = *(const uint4*)&g_c1b[(size_t)(p0 + r) * DF + kc * 128 + cc * 8];
            uint4 vb = *(const uint4*)&g_c2b[(size_t)(q0 + r) * DF + kc * 128 + cc * 8];
            *(uint4*)(sm + SM_A + r * (PADROW * 2) + cc * 16) = va;
            *(uint4*)(sm + SM_B + r * (PADROW * 2) + cc * 16) = vb;
        }
        __syncthreads();

        #pragma unroll
        for (int ks = 0; ks < 8; ks++) {        // chunk K=128 -> 8 steps of 16
            const uint32_t ko = ks * 32;
            uint32_t a[2][4], b[8][2];
            #pragma unroll
            for (int i = 0; i < 2; i++)
                LDSM_X4(a[i][0], a[i][1], a[i][2], a[i][3], aAddr[i] + ko);
            #pragma unroll
            for (int jp = 0; jp < 4; jp++)
                LDSM_X4(b[2 * jp][0], b[2 * jp][1], b[2 * jp + 1][0], b[2 * jp + 1][1],
                        bAddr[jp] + ko);
            #pragma unroll
            for (int i = 0; i < 2; i++)
                #pragma unroll
                for (int j = 0; j < 8; j++)
                    MMA16816(c[i][j], a[i][0], a[i][1], a[i][2], a[i][3], b[j][0], b[j][1]);
        }
        __syncthreads();    // tiles reused next chunk
    }

    // epilogue: d2 = sp + sq - 2*dot (fp16), pair-merged histogram, store
    const float* sps = (const float*)(sm + SM_SP);
    const float* sqs = (const float*)(sm + SM_SQ);

    #pragma unroll
    for (int i = 0; i < 2; i++) {
        const int r0 = mbase + i * 16 + (lane >> 2);
        const float sp0 = sps[r0], sp1 = sps[r0 + 8];
        #pragma unroll
        for (int j = 0; j < 8; j++) {
            const int cl = nbase + j * 8 + (lane & 3) * 2;
            const float sq0 = sqs[cl], sq1 = sqs[cl + 1];
            float d0 = fmaxf(sp0 + sq0 - 2.f * c[i][j][0], 0.f);
            float d1 = fmaxf(sp0 + sq1 - 2.f * c[i][j][1], 0.f);
            float d2v = fmaxf(sp1 + sq0 - 2.f * c[i][j][2], 0.f);
            float d3 = fmaxf(sp1 + sq1 - 2.f * c[i][j][3], 0.f);
            __half2 h01 = __floats2half2_rn(d0, d1);
            __half2 h23 = __floats2half2_rn(d2v, d3);

            unsigned u01 = *(unsigned*)&h01, u23 = *(unsigned*)&h23;
            unsigned b0 = (u01 & 0xFFFFu) >> 4, b1 = u01 >> 20;
            unsigned b2 = (u23 & 0xFFFFu) >> 4, b3 = u23 >> 20;
            if (b0 == b1) atomicAdd(&hist[b0], 2u);
            else { atomicAdd(&hist[b0], 1u); atomicAdd(&hist[b1], 1u); }
            if (b2 == b3) atomicAdd(&hist[b2], 2u);
            else { atomicAdd(&hist[b2], 1u); atomicAdd(&hist[b3], 1u); }

            *(__half2*)&g_d2h[(size_t)(p0 + r0)     * NP + q0 + cl] = h01;
            *(__half2*)&g_d2h[(size_t)(p0 + r0 + 8) * NP + q0 + cl] = h23;
        }
    }
    __syncthreads();
    for (int i = t; i < NBINS; i += 256) {
        unsigned h = hist[i];
        if (h) atomicAdd(&g_hist[i], h);
    }
}

// parallel suffix-scan threshold: bin containing the rank-TOPK value
__global__ __launch_bounds__(1024) void k_thresh() {
    __shared__ unsigned scan[1024];
    const int t = threadIdx.x;
    const int btop = NBINS - 1 - 2 * t;          // group t: 2 bins descending
    unsigned h0 = g_hist[btop], h1 = g_hist[btop - 1];
    unsigned p = h0 + h1;
    scan[t] = p;
    __syncthreads();
    #pragma unroll
    for (int o = 1; o < 1024; o <<= 1) {
        unsigned v = (t >= o) ? scan[t - o] : 0u;
        __syncthreads();
        if (t >= o) scan[t] += v;
        __syncthreads();
    }
    unsigned excl = scan[t] - p;
    if (excl < TOPK && excl + p >= TOPK) {       // exactly one thread crosses
        unsigned cum = excl + h0;
        g_threshBin = (cum >= TOPK) ? btop : btop - 1;
    }
}

// compact all fp16 values whose bin >= threshold
__global__ void k_compact() {
    size_t i = (size_t)blockIdx.x * blockDim.x + threadIdx.x;
    const uint4 v = ((const uint4*)g_d2h)[i];      // 8 halves
    const unsigned tb = (unsigned)g_threshBin;
    unsigned words[4] = {v.x, v.y, v.z, v.w};
    #pragma unroll
    for (int wI = 0; wI < 4; wI++) {
        unsigned lo = words[wI] & 0xFFFFu, hi = words[wI] >> 16;
        if ((lo >> 4) >= tb) {
            int p = atomicAdd(&g_candCount, 1);
            if (p < CAP) g_cand[p] = __half2float(__ushort_as_half((unsigned short)lo));
        }
        if ((hi >> 4) >= tb) {
            int p = atomicAdd(&g_candCount, 1);
            if (p < CAP) g_cand[p] = __half2float(__ushort_as_half((unsigned short)hi));
        }
    }
}

// exact top-100 over candidates, mean of sqrt (descending -> deterministic)
__global__ __launch_bounds__(1024) void k_select(float* __restrict__ out) {
    __shared__ float red[1024];
    __shared__ int   redi[1024];
    __shared__ float s_sum;
    const int t = threadIdx.x;
    int n = g_candCount;
    if (n > CAP) n = CAP;
    if (t == 0) s_sum = 0.f;
    __syncthreads();

    for (int it = 0; it < TOPK; it++) {
        float m = -1.f; int mi = -1;
        for (int i = t; i < n; i += 1024) {
            float v = g_cand[i];
            if (v > m) { m = v; mi = i; }
        }
        red[t] = m; redi[t] = mi;
        __syncthreads();
        #pragma unroll
        for (int s = 512; s > 0; s >>= 1) {
            if (t < s && red[t + s] > red[t]) { red[t] = red[t + s]; redi[t] = redi[t + s]; }
            __syncthreads();
        }
        if (t == 0 && redi[0] >= 0) {
            s_sum += sqrtf(red[0]);
            g_cand[redi[0]] = -1.f;
        }
        __syncthreads();
    }
    if (t == 0) *out = s_sum / (float)TOPK;
}

extern "C" void kernel_launch(void* const* d_in, const int* in_sizes, int n_in,
                              void* d_out, int out_size) {
    const float* fm   = (const float*)d_in[0];
    const int*   ids1 = (const int*)d_in[1];
    const int*   ids2 = (const int*)d_in[2];
    float* out = (float*)d_out;

    static int smem_set = 0;
    if (!smem_set) {
        cudaFuncSetAttribute(k_dist, cudaFuncAttributeMaxDynamicSharedMemorySize, SM_TOT);
        smem_set = 1;
    }

    k_init<<<(NBINS + 255) / 256, 256>>>();
    k_gather<<<dim3(NP, 2), 64>>>(fm, ids1, ids2);
    k_dist<<<dim3(NP / 128, NP / 128), 256, SM_TOT>>>();
    k_thresh<<<1, 1024>>>();
    k_compact<<<(NP * NP / 8) / 256, 256>>>();   // uint4 = 8 halves per thread
    k_select<<<1, 1024>>>(out);
}

// round 9
// speedup vs baseline: 2.9168x; 2.0370x over previous
#include <cuda_runtime.h>
#include <cuda_bf16.h>
#include <cuda_fp16.h>
#include <stdint.h>

#define NP     4096
#define DF     256
#define TOPK   100
#define NBINS  2048      // coarse: fp16 bits >> 4
#define NCODES 32768     // fine: full positive fp16 code space

// ---- scratch (static device globals; no allocation in kernel_launch) ----
__device__ __nv_bfloat16 g_c1b[NP * DF];
__device__ __nv_bfloat16 g_c2b[NP * DF];
__device__ float         g_sq1[NP];
__device__ float         g_sq2[NP];
__device__ __half        g_d2h[(size_t)NP * NP];   // 32 MB fp16 squared distances
__device__ unsigned int  g_hist[NBINS];
__device__ unsigned int  g_hist2[NCODES];          // exact per-fp16-code counts
__device__ int           g_threshBin;

__device__ __forceinline__ uint32_t smem_u32(const void* p) {
    uint32_t a;
    asm("{ .reg .u64 t; cvta.to.shared.u64 t, %1; cvt.u32.u64 %0, t; }" : "=r"(a) : "l"(p));
    return a;
}

#define LDSM_X4(r0, r1, r2, r3, addr)                                          \
    asm volatile("ldmatrix.sync.aligned.m8n8.x4.shared.b16 {%0,%1,%2,%3}, [%4];" \
        : "=r"(r0), "=r"(r1), "=r"(r2), "=r"(r3) : "r"(addr))

#define MMA16816(c, a0, a1, a2, a3, b0, b1)                                    \
    asm volatile("mma.sync.aligned.m16n8k16.row.col.f32.bf16.bf16.f32 "        \
        "{%0,%1,%2,%3}, {%4,%5,%6,%7}, {%8,%9}, {%0,%1,%2,%3};"                \
        : "+f"((c)[0]), "+f"((c)[1]), "+f"((c)[2]), "+f"((c)[3])               \
        : "r"(a0), "r"(a1), "r"(a2), "r"(a3), "r"(b0), "r"(b1))

// ---- dynamic SMEM layout for k_dist (bytes) ----
// K in 2 chunks of 128: tiles 128 rows x 136 bf16 (272 B rows, conflict-free ldmatrix)
#define PADROW  136
#define SM_SP   0                          // 128 f32
#define SM_SQ   512                        // 128 f32
#define SM_A    1024                       // 128*272 = 34816
#define SM_B    (SM_A + 128 * PADROW * 2)
#define SM_TOT  (SM_B + 128 * PADROW * 2)  // 70656 -> 2 CTAs/SM

// ================= kernels =================

__global__ void k_init() {
    int i = blockIdx.x * blockDim.x + threadIdx.x;
    if (i < NBINS)  g_hist[i]  = 0u;
    if (i < NCODES) g_hist2[i] = 0u;
}

// gather picked rows (-> bf16 copies) + exact fp32 squared norms
__global__ void k_gather(const float* __restrict__ fm,
                         const int* __restrict__ ids1,
                         const int* __restrict__ ids2) {
    int row = blockIdx.x;
    const int* ids = blockIdx.y ? ids2 : ids1;
    __nv_bfloat16* C = blockIdx.y ? g_c2b : g_c1b;
    float*        SQ = blockIdx.y ? g_sq2 : g_sq1;

    int id = ids[row];
    float4 v = ((const float4*)(fm + (size_t)id * DF))[threadIdx.x];  // 64 thr * 4

    unsigned lo = ((unsigned)__bfloat16_as_ushort(__float2bfloat16(v.y)) << 16) |
                   (unsigned)__bfloat16_as_ushort(__float2bfloat16(v.x));
    unsigned hi = ((unsigned)__bfloat16_as_ushort(__float2bfloat16(v.w)) << 16) |
                   (unsigned)__bfloat16_as_ushort(__float2bfloat16(v.z));
    *(uint2*)&C[(size_t)row * DF + threadIdx.x * 4] = make_uint2(lo, hi);

    float s = v.x * v.x + v.y * v.y + v.z * v.z + v.w * v.w;
    #pragma unroll
    for (int o = 16; o; o >>= 1) s += __shfl_down_sync(0xffffffffu, s, o);
    __shared__ float ws[2];
    if ((threadIdx.x & 31) == 0) ws[threadIdx.x >> 5] = s;
    __syncthreads();
    if (threadIdx.x == 0) SQ[row] = ws[0] + ws[1];
}

// 128x128 tile of squared distances via bf16 mma.sync; pure GEMM + fp16 store
__global__ __launch_bounds__(256, 2) void k_dist() {
    extern __shared__ char sm[];
    const uint32_t sb = smem_u32(sm);
    const int t = threadIdx.x, lane = t & 31, w = t >> 5;
    const int p0 = blockIdx.y * 128, q0 = blockIdx.x * 128;

    if (t < 128)       ((float*)(sm + SM_SP))[t]       = g_sq1[p0 + t];
    else               ((float*)(sm + SM_SQ))[t - 128] = g_sq2[q0 + t - 128];

    const int mbase = (w & 3) * 32;     // 4 warps along M
    const int nbase = (w >> 2) * 64;    // 2 warps along N

    uint32_t aAddr[2], bAddr[4];
    #pragma unroll
    for (int i = 0; i < 2; i++) {
        int row = mbase + i * 16 + (lane & 15);
        aAddr[i] = sb + SM_A + row * (PADROW * 2) + (lane >> 4) * 16;
    }
    #pragma unroll
    for (int jp = 0; jp < 4; jp++) {
        int row = nbase + jp * 16 + (lane & 7) + ((lane >> 4) & 1) * 8;
        bAddr[jp] = sb + SM_B + row * (PADROW * 2) + ((lane >> 3) & 1) * 16;
    }

    float c[2][8][4];
    #pragma unroll
    for (int i = 0; i < 2; i++)
        #pragma unroll
        for (int j = 0; j < 8; j++)
            #pragma unroll
            for (int r = 0; r < 4; r++) c[i][j][r] = 0.f;

    for (int kc = 0; kc < 2; kc++) {
        #pragma unroll
        for (int i = 0; i < 8; i++) {
            int idx = i * 256 + t;
            int r = idx >> 4, cc = idx & 15;
            uint4 va = *(const uint4*)&g_c1b[(size_t)(p0 + r) * DF + kc * 128 + cc * 8];
            uint4 vb = *(const uint4*)&g_c2b[(size_t)(q0 + r) * DF + kc * 128 + cc * 8];
            *(uint4*)(sm + SM_A + r * (PADROW * 2) + cc * 16) = va;
            *(uint4*)(sm + SM_B + r * (PADROW * 2) + cc * 16) = vb;
        }
        __syncthreads();

        #pragma unroll
        for (int ks = 0; ks < 8; ks++) {
            const uint32_t ko = ks * 32;
            uint32_t a[2][4], b[8][2];
            #pragma unroll
            for (int i = 0; i < 2; i++)
                LDSM_X4(a[i][0], a[i][1], a[i][2], a[i][3], aAddr[i] + ko);
            #pragma unroll
            for (int jp = 0; jp < 4; jp++)
                LDSM_X4(b[2 * jp][0], b[2 * jp][1], b[2 * jp + 1][0], b[2 * jp + 1][1],
                        bAddr[jp] + ko);
            #pragma unroll
            for (int i = 0; i < 2; i++)
                #pragma unroll
                for (int j = 0; j < 8; j++)
                    MMA16816(c[i][j], a[i][0], a[i][1], a[i][2], a[i][3], b[j][0], b[j][1]);
        }
        __syncthreads();
    }

    // epilogue: d2 = sp + sq - 2*dot -> fp16 store (no histogram here)
    const float* sps = (const float*)(sm + SM_SP);
    const float* sqs = (const float*)(sm + SM_SQ);
    #pragma unroll
    for (int i = 0; i < 2; i++) {
        const int r0 = mbase + i * 16 + (lane >> 2);
        const float sp0 = sps[r0], sp1 = sps[r0 + 8];
        #pragma unroll
        for (int j = 0; j < 8; j++) {
            const int cl = nbase + j * 8 + (lane & 3) * 2;
            const float sq0 = sqs[cl], sq1 = sqs[cl + 1];
            float d0 = fmaxf(sp0 + sq0 - 2.f * c[i][j][0], 0.f);
            float d1 = fmaxf(sp0 + sq1 - 2.f * c[i][j][1], 0.f);
            float d2v = fmaxf(sp1 + sq0 - 2.f * c[i][j][2], 0.f);
            float d3 = fmaxf(sp1 + sq1 - 2.f * c[i][j][3], 0.f);
            *(__half2*)&g_d2h[(size_t)(p0 + r0)     * NP + q0 + cl] = __floats2half2_rn(d0, d1);
            *(__half2*)&g_d2h[(size_t)(p0 + r0 + 8) * NP + q0 + cl] = __floats2half2_rn(d2v, d3);
        }
    }
}

// dedicated coarse histogram over the fp16 d2 buffer (L2-resident)
__global__ __launch_bounds__(256) void k_hist() {
    __shared__ unsigned hist[NBINS];
    for (int i = threadIdx.x; i < NBINS; i += 256) hist[i] = 0u;
    __syncthreads();

    const uint4* p = (const uint4*)g_d2h;
    size_t base = (size_t)blockIdx.x * (256 * 8);
    #pragma unroll
    for (int r = 0; r < 8; r++) {
        uint4 v = p[base + r * 256 + threadIdx.x];
        unsigned wd[4] = {v.x, v.y, v.z, v.w};
        #pragma unroll
        for (int k = 0; k < 4; k++) {
            unsigned b0 = (wd[k] & 0xFFFFu) >> 4, b1 = wd[k] >> 20;
            if (b0 == b1) atomicAdd(&hist[b0], 2u);
            else { atomicAdd(&hist[b0], 1u); atomicAdd(&hist[b1], 1u); }
        }
    }
    __syncthreads();
    for (int i = threadIdx.x; i < NBINS; i += 256) {
        unsigned h = hist[i];
        if (h) atomicAdd(&g_hist[i], h);
    }
}

// parallel suffix-scan threshold: coarse bin containing the rank-TOPK value
__global__ __launch_bounds__(1024) void k_thresh() {
    __shared__ unsigned scan[1024];
    const int t = threadIdx.x;
    const int btop = NBINS - 1 - 2 * t;
    unsigned h0 = g_hist[btop], h1 = g_hist[btop - 1];
    unsigned p = h0 + h1;
    scan[t] = p;
    __syncthreads();
    #pragma unroll
    for (int o = 1; o < 1024; o <<= 1) {
        unsigned v = (t >= o) ? scan[t - o] : 0u;
        __syncthreads();
        if (t >= o) scan[t] += v;
        __syncthreads();
    }
    unsigned excl = scan[t] - p;
    if (excl < TOPK && excl + p >= TOPK) {
        unsigned cum = excl + h0;
        g_threshBin = (cum >= TOPK) ? btop : btop - 1;
    }
}

// candidates (coarse bin >= threshold) -> exact per-code counts
__global__ void k_compact() {
    size_t i = (size_t)blockIdx.x * blockDim.x + threadIdx.x;
    const uint4 v = ((const uint4*)g_d2h)[i];      // 8 halves
    const unsigned tb = (unsigned)g_threshBin;
    unsigned words[4] = {v.x, v.y, v.z, v.w};
    #pragma unroll
    for (int wI = 0; wI < 4; wI++) {
        unsigned lo = words[wI] & 0xFFFFu, hi = words[wI] >> 16;
        if ((lo >> 4) >= tb) atomicAdd(&g_hist2[lo], 1u);
        if ((hi >> 4) >= tb) atomicAdd(&g_hist2[hi], 1u);
    }
}

// closed-form exact top-100: suffix scan over fp16 codes, weighted sqrt sum
__global__ __launch_bounds__(1024) void k_select(float* __restrict__ out) {
    __shared__ unsigned scan[1024];
    __shared__ float    part[1024];
    const int t = threadIdx.x;

    // thread t covers 32 codes descending: chi, chi-1, ..., chi-31
    const int chi = NCODES - 1 - 32 * t;
    unsigned cnt[32];
    unsigned csum = 0;
    #pragma unroll
    for (int j = 0; j < 32; j++) { cnt[j] = g_hist2[chi - j]; csum += cnt[j]; }

    scan[t] = csum;
    __syncthreads();
    #pragma unroll
    for (int o = 1; o < 1024; o <<= 1) {
        unsigned v = (t >= o) ? scan[t - o] : 0u;
        __syncthreads();
        if (t >= o) scan[t] += v;
        __syncthreads();
    }
    const unsigned excl = scan[t] - csum;   // total count in codes above this chunk

    float psum = 0.f;
    if (excl < TOPK) {
        unsigned quota = TOPK - excl;       // how many we may still take
        #pragma unroll
        for (int j = 0; j < 32; j++) {
            if (quota == 0) break;
            unsigned c = cnt[j];
            if (c) {
                unsigned take = c < quota ? c : quota;
                float val = __half2float(__ushort_as_half((unsigned short)(chi - j)));
                psum += (float)take * sqrtf(val);
                quota -= take;
            }
        }
    }
    part[t] = psum;
    __syncthreads();
    #pragma unroll
    for (int s = 512; s > 0; s >>= 1) {
        if (t < s) part[t] += part[t + s];
        __syncthreads();
    }
    if (t == 0) *out = part[0] / (float)TOPK;
}

extern "C" void kernel_launch(void* const* d_in, const int* in_sizes, int n_in,
                              void* d_out, int out_size) {
    const float* fm   = (const float*)d_in[0];
    const int*   ids1 = (const int*)d_in[1];
    const int*   ids2 = (const int*)d_in[2];
    float* out = (float*)d_out;

    static int smem_set = 0;
    if (!smem_set) {
        cudaFuncSetAttribute(k_dist, cudaFuncAttributeMaxDynamicSharedMemorySize, SM_TOT);
        smem_set = 1;
    }

    k_init<<<(NCODES + 255) / 256, 256>>>();
    k_gather<<<dim3(NP, 2), 64>>>(fm, ids1, ids2);
    k_dist<<<dim3(NP / 128, NP / 128), 256, SM_TOT>>>();
    k_hist<<<NP * NP / (256 * 8 * 8), 256>>>();
    k_thresh<<<1, 1024>>>();
    k_compact<<<(NP * NP / 8) / 256, 256>>>();   // uint4 = 8 halves per thread
    k_select<<<1, 1024>>>(out);
}